// round 12
// baseline (speedup 1.0000x reference)
#include <cuda_runtime.h>

// Reverse (suffix) cummax along axis 1 of [B=16, H=128, W=128, C=256] fp32.
//
// R10: continue the sync-domain axis (2 dom -> 78.5% DRAM, 4 dom -> 79.9%):
// 128-thread blocks = 16 segments x 8 c4-lanes, __launch_bounds__(128,8)
// -> 8 co-resident independent sync domains per SM (32 warps total). While
// some blocks sit in their sync/carry/store phase, seven others keep the
// HBM read queue fed. Warp load = 4x128B lines (4 segments x 8 lanes), each
// line fully consumed -> coalescing preserved.
//
// Per block-slab:
//  - Thread owns an 8-element h-segment of one float4 column.
//  - Phase 1: 8 independent coalesced streaming loads.
//  - Phase 2: in-register local suffix max; segment maxes via 2KB smem;
//    carry = max over later segments.
//  - Phase 3: 8 coalesced streaming stores.
// Traffic exactly read-once / write-once (512 MB).

#define B_DIM 16
#define H_DIM 128
#define W_DIM 128
#define C_DIM 256

#define C4      (C_DIM / 4)     // 64 float4 per (b,h,w) row
#define STRIDE4 (W_DIM * C4)    // 8192 float4 between consecutive h

#define SEG_LEN  8                   // h elements per thread
#define NSEG     (H_DIM / SEG_LEN)   // 16 segments per column
#define LANES    8                   // c4 lanes per block (eighth of C4)
#define THREADS  (NSEG * LANES)      // 128
#define BLOCKS   (B_DIM * W_DIM * (C4 / LANES))  // 16384

__device__ __forceinline__ float4 f4max(float4 a, float4 b) {
    float4 r;
    r.x = fmaxf(a.x, b.x);
    r.y = fmaxf(a.y, b.y);
    r.z = fmaxf(a.z, b.z);
    r.w = fmaxf(a.w, b.w);
    return r;
}

__global__ void __launch_bounds__(THREADS, 8)
leftpool_rev_cummax_o_kernel(const float4* __restrict__ in,
                             float4* __restrict__ out) {
    __shared__ float4 segmax[NSEG * LANES];   // 2 KB

    const int seg  = threadIdx.x >> 3;        // 0..15 (segment)
    const int lane = threadIdx.x & 7;         // 0..7  (c4 within eighth)

    // blockIdx.x = (b * W + w) * 8 + eighth
    const int eighth = blockIdx.x & 7;
    const int bw     = blockIdx.x >> 3;       // b*W + w
    const int b = bw >> 7;                    // W_DIM = 128
    const int w = bw & (W_DIM - 1);
    const int c4 = eighth * LANES + lane;

    // float4 offset of (b, h = seg*SEG_LEN, w, c4)
    const int base = ((b * H_DIM + seg * SEG_LEN) * W_DIM + w) * C4 + c4;

    // ---- Phase 1: burst load my segment (8 independent coalesced loads)
    float4 v[SEG_LEN];
    #pragma unroll
    for (int i = 0; i < SEG_LEN; ++i)
        v[i] = __ldcs(&in[base + i * STRIDE4]);

    // ---- Phase 2a: local (within-segment) suffix max, in registers
    #pragma unroll
    for (int i = SEG_LEN - 2; i >= 0; --i)
        v[i] = f4max(v[i], v[i + 1]);

    segmax[seg * LANES + lane] = v[0];
    __syncthreads();

    // ---- Phase 2b: carry = max over all later segments (same column)
    float4 carry;
    carry.x = carry.y = carry.z = carry.w = __int_as_float(0xff800000); // -inf
    for (int t = seg + 1; t < NSEG; ++t)
        carry = f4max(carry, segmax[t * LANES + lane]);

    #pragma unroll
    for (int i = 0; i < SEG_LEN; ++i)
        v[i] = f4max(v[i], carry);

    // ---- Phase 3: burst store (8 coalesced streaming stores)
    #pragma unroll
    for (int i = 0; i < SEG_LEN; ++i)
        __stcs(&out[base + i * STRIDE4], v[i]);
}

extern "C" void kernel_launch(void* const* d_in, const int* in_sizes, int n_in,
                              void* d_out, int out_size) {
    const float4* in  = (const float4*)d_in[0];
    float4*       out = (float4*)d_out;
    leftpool_rev_cummax_o_kernel<<<BLOCKS, THREADS>>>(in, out);
}

// round 13
// speedup vs baseline: 1.0039x; 1.0039x over previous
#include <cuda_runtime.h>

// Reverse (suffix) cummax along axis 1 of [B=16, H=128, W=128, C=256] fp32.
//
// R12 = R9 (best measured config: 4 independent 256-thread sync domains/SM,
// burst-separated segmented scan, DRAM 79.9% / 6.33 TB/s) with index-ALU
// trimmed (shift/mask instead of div/mod; single hoisted base). The
// R3..R10 sweep showed warp count, burst length, domain count and
// persistence are all exhausted axes: ~6.33 TB/s is the controller-level
// ceiling for this 1:1 read/write streaming mix.
//
// Per block-slab:
//  - Thread owns an 8-element h-segment of one float4 column.
//  - Block = 256 thr = 16 segments x 16 c4-lanes (one C-quarter of one
//    (b,w) column set).
//  - Phase 1: 8 independent coalesced streaming loads (burst read).
//  - Phase 2: in-register local suffix max; per-segment maxes via 4KB smem;
//    carry = max over later segments.
//  - Phase 3: 8 coalesced streaming stores (burst write).
// Traffic exactly read-once / write-once (512 MB).

#define B_DIM 16
#define H_DIM 128
#define W_DIM 128
#define C_DIM 256

#define C4      (C_DIM / 4)     // 64 float4 per (b,h,w) row
#define STRIDE4 (W_DIM * C4)    // 8192 float4 between consecutive h

#define SEG_LEN  8                   // h elements per thread
#define NSEG     (H_DIM / SEG_LEN)   // 16 segments per column
#define LANES    16                  // c4 lanes per block (quarter of C4)
#define THREADS  (NSEG * LANES)      // 256
#define BLOCKS   (B_DIM * W_DIM * (C4 / LANES))  // 8192

__device__ __forceinline__ float4 f4max(float4 a, float4 b) {
    float4 r;
    r.x = fmaxf(a.x, b.x);
    r.y = fmaxf(a.y, b.y);
    r.z = fmaxf(a.z, b.z);
    r.w = fmaxf(a.w, b.w);
    return r;
}

__global__ void __launch_bounds__(THREADS, 4)
leftpool_rev_cummax_r12_kernel(const float4* __restrict__ in,
                               float4* __restrict__ out) {
    __shared__ float4 segmax[NSEG * LANES];   // 4 KB

    const int seg  = threadIdx.x >> 4;        // 0..15 (segment)
    const int lane = threadIdx.x & 15;        // 0..15 (c4 within quarter)

    // blockIdx.x = ((b << 7) | w) * 4 + quarter   (W_DIM = 128)
    const int quarter = blockIdx.x & 3;
    const int bw      = blockIdx.x >> 2;      // b*128 + w
    const int b       = bw >> 7;
    const int w       = bw & (W_DIM - 1);
    const int c4      = (quarter << 4) | lane;

    // float4 offset of (b, h = seg*SEG_LEN, w, c4)
    const int base = ((b * H_DIM + (seg << 3)) * W_DIM + w) * C4 + c4;

    // ---- Phase 1: burst load my segment (8 independent coalesced loads)
    float4 v[SEG_LEN];
    #pragma unroll
    for (int i = 0; i < SEG_LEN; ++i)
        v[i] = __ldcs(&in[base + i * STRIDE4]);

    // ---- Phase 2a: local (within-segment) suffix max, in registers
    #pragma unroll
    for (int i = SEG_LEN - 2; i >= 0; --i)
        v[i] = f4max(v[i], v[i + 1]);

    segmax[(seg << 4) | lane] = v[0];
    __syncthreads();

    // ---- Phase 2b: carry = max over all later segments (same column)
    float4 carry;
    carry.x = carry.y = carry.z = carry.w = __int_as_float(0xff800000); // -inf
    for (int t = seg + 1; t < NSEG; ++t)
        carry = f4max(carry, segmax[(t << 4) | lane]);

    #pragma unroll
    for (int i = 0; i < SEG_LEN; ++i)
        v[i] = f4max(v[i], carry);

    // ---- Phase 3: burst store (8 coalesced streaming stores)
    #pragma unroll
    for (int i = 0; i < SEG_LEN; ++i)
        __stcs(&out[base + i * STRIDE4], v[i]);
}

extern "C" void kernel_launch(void* const* d_in, const int* in_sizes, int n_in,
                              void* d_out, int out_size) {
    const float4* in  = (const float4*)d_in[0];
    float4*       out = (float4*)d_out;
    leftpool_rev_cummax_r12_kernel<<<BLOCKS, THREADS>>>(in, out);
}